// round 11
// baseline (speedup 1.0000x reference)
#include <cuda_runtime.h>
#include <cuda_fp16.h>
#include <cstdint>

// Problem constants
#define B_  32
#define T_  64
#define V_  50257
#define E_  256
#define H_  512
#define G4_ 2048   // 4*H
#define H2_ 1024   // 2*H
#define M_  2048   // T*B
#define VPAD2_ 50432  // 197*256

// K5 tiling: CTA 128x256, 512 threads (16 warps 2x8), warp tile 64x32, BK=128
#define BM_ 128
#define BN_ 256
#define BKC_ 128
#define NKT_ (H2_ / BKC_)         // 8 chunks
#define ST_A_BYTES 32768          // 128*128*2
#define ST_B_BYTES 65536          // 256*128*2
#define ST_BYTES   98304
#define SMEM_DYN   (2 * ST_BYTES) // 196608

// ---------------- scratch (device globals; no allocation allowed) ----------------
__device__ float g_base[B_ * G4_];
__device__ float g_xg[M_ * G4_];
__device__ float g_hs[M_ * H_];
__device__ float g_hid[M_ * H2_];
__device__ __align__(16) __half g_hidp[(size_t)M_ * H2_];           // fp16 fragment-permuted
__device__ __align__(16) __half g_w2p[(size_t)VPAD2_ * H2_];        // fp16 fragment-permuted, padded

// ---------------- helpers ----------------
// f16-accumulate mma: d(f16x2 pair) = A.B (c = 0)  -> promoted by caller
__device__ __forceinline__ void mma_f16acc(uint32_t& d0, uint32_t& d1,
                                           const uint32_t* a, uint32_t b0, uint32_t b1) {
    asm volatile(
        "mma.sync.aligned.m16n8k16.row.col.f16.f16.f16.f16 "
        "{%0,%1}, {%2,%3,%4,%5}, {%6,%7}, {%8,%8};\n"
        : "=r"(d0), "=r"(d1)
        : "r"(a[0]), "r"(a[1]), "r"(a[2]), "r"(a[3]), "r"(b0), "r"(b1), "r"(0u));
}

__device__ __forceinline__ float sigf(float x) {
    return __fdividef(1.f, 1.f + __expf(-x));
}
__device__ __forceinline__ float ftanh(float x) {
    float e = __expf(2.f * x);
    return 1.f - __fdividef(2.f, e + 1.f);
}

__device__ __forceinline__ uint32_t smem_u32(const void* p) {
    return (uint32_t)__cvta_generic_to_shared(p);
}

__device__ __forceinline__ void cp16(uint32_t dst, const void* src) {
    asm volatile("cp.async.cg.shared.global [%0], [%1], 16;\n"
                 :: "r"(dst), "l"(src) : "memory");
}

__device__ __forceinline__ uint32_t pack2(float lo, float hi) {
    __half2 h = __floats2half2_rn(lo, hi);
    return *(uint32_t*)&h;
}

// ---------------- K1: base gates = features @ W_hh^T + b_ih + b_hh ----------------
__global__ void base_kernel(const float* __restrict__ feat,
                            const float* __restrict__ W_hh,
                            const float* __restrict__ b_ih,
                            const float* __restrict__ b_hh,
                            float* __restrict__ base) {
    __shared__ float4 f4[H_ / 4];
    int b = blockIdx.x;
    if (threadIdx.x < H_ / 4)
        f4[threadIdx.x] = ((const float4*)(feat + (size_t)b * H_))[threadIdx.x];
    __syncthreads();
    for (int g = threadIdx.x; g < G4_; g += blockDim.x) {
        const float4* w4 = (const float4*)(W_hh + (size_t)g * H_);
        float s = 0.f;
        #pragma unroll 8
        for (int k = 0; k < H_ / 4; k++) {
            float4 w = w4[k], f = f4[k];
            s += w.x * f.x + w.y * f.y + w.z * f.z + w.w * f.w;
        }
        base[b * G4_ + g] = s + b_ih[g] + b_hh[g];
    }
}

// ---------------- generic 128x128x8 SGEMM (2 CTAs/SM) ----------------
__global__ __launch_bounds__(256, 2)
void sgemm_tn(const float* __restrict__ A, const float* __restrict__ Bm,
              const float* __restrict__ bias, float* __restrict__ C,
              int M, int N, int K,
              const int* __restrict__ captions, const float* __restrict__ embA) {
    __shared__ float As[8][132];
    __shared__ float Bs[8][132];
    int tid = threadIdx.x;
    int tx = tid & 15, ty = tid >> 4;
    int m0 = blockIdx.y * 128, n0 = blockIdx.x * 128;

    float acc[8][8];
    #pragma unroll
    for (int i = 0; i < 8; i++)
        #pragma unroll
        for (int j = 0; j < 8; j++) acc[i][j] = 0.f;

    int lrow = tid >> 1;
    int lkq  = tid & 1;
    const float* arow;
    if (captions) {
        int m = m0 + lrow;
        int bb = m & 31, tt = m >> 5;
        int ct = (tt == 0) ? 0 : (tt - 1);
        int tok = captions[bb * T_ + ct];
        arow = embA + (size_t)tok * K;
    } else {
        arow = A + (size_t)(m0 + lrow) * K;
    }
    const float* brow = Bm + (size_t)(n0 + lrow) * K;

    for (int k0 = 0; k0 < K; k0 += 8) {
        float4 va = *(const float4*)(arow + k0 + lkq * 4);
        float4 vb = *(const float4*)(brow + k0 + lkq * 4);
        As[lkq * 4 + 0][lrow] = va.x; As[lkq * 4 + 1][lrow] = va.y;
        As[lkq * 4 + 2][lrow] = va.z; As[lkq * 4 + 3][lrow] = va.w;
        Bs[lkq * 4 + 0][lrow] = vb.x; Bs[lkq * 4 + 1][lrow] = vb.y;
        Bs[lkq * 4 + 2][lrow] = vb.z; Bs[lkq * 4 + 3][lrow] = vb.w;
        __syncthreads();
        #pragma unroll
        for (int kk = 0; kk < 8; kk++) {
            float a[8], b[8];
            *(float4*)&a[0] = *(float4*)&As[kk][ty * 8];
            *(float4*)&a[4] = *(float4*)&As[kk][ty * 8 + 4];
            *(float4*)&b[0] = *(float4*)&Bs[kk][tx * 8];
            *(float4*)&b[4] = *(float4*)&Bs[kk][tx * 8 + 4];
            #pragma unroll
            for (int i = 0; i < 8; i++)
                #pragma unroll
                for (int j = 0; j < 8; j++) acc[i][j] += a[i] * b[j];
        }
        __syncthreads();
    }

    float bv[8];
    if (bias) {
        *(float4*)&bv[0] = *(const float4*)(bias + n0 + tx * 8);
        *(float4*)&bv[4] = *(const float4*)(bias + n0 + tx * 8 + 4);
    } else {
        #pragma unroll
        for (int j = 0; j < 8; j++) bv[j] = 0.f;
    }

    #pragma unroll
    for (int i = 0; i < 8; i++) {
        int m = m0 + ty * 8 + i;
        float* crow = C + (size_t)m * N + n0 + tx * 8;
        float o[8];
        #pragma unroll
        for (int j = 0; j < 8; j++) o[j] = acc[i][j] + bv[j];
        *(float4*)&crow[0] = *(float4*)&o[0];
        *(float4*)&crow[4] = *(float4*)&o[4];
    }
}

// ---------------- K3: LSTM scan (depth-8 prefetch) ----------------
__global__ void lstm_scan(const float* __restrict__ xg,
                          const float* __restrict__ base,
                          float* __restrict__ hs) {
    int idx = blockIdx.x * blockDim.x + threadIdx.x;
    int b = idx >> 9, h = idx & 511;
    float bi = base[b * G4_ + h];
    float bff = base[b * G4_ + H_ + h];
    float bg = base[b * G4_ + 2 * H_ + h];
    float bo = base[b * G4_ + 3 * H_ + h];

    const float* xr = xg + (size_t)b * G4_ + h;
    const size_t step = (size_t)B_ * G4_;

    float4 pf[8];
    #pragma unroll
    for (int j = 0; j < 8; j++) {
        const float* p = xr + (size_t)j * step;
        pf[j] = make_float4(p[0], p[H_], p[2 * H_], p[3 * H_]);
    }

    float c = 0.f;
    float* hp = hs + (size_t)b * H_ + h;
    #pragma unroll 8
    for (int t = 0; t < T_; t++) {
        float4 cur = pf[t & 7];
        if (t + 8 < T_) {
            const float* p = xr + (size_t)(t + 8) * step;
            pf[t & 7] = make_float4(p[0], p[H_], p[2 * H_], p[3 * H_]);
        }
        float i = sigf(cur.x + bi);
        float f = sigf(cur.y + bff);
        float g = ftanh(cur.z + bg);
        float o = sigf(cur.w + bo);
        c = f * c + i * g;
        hp[(size_t)t * B_ * H_] = o * ftanh(c);
    }
}

// ---------------- prep: permute hid (fp32) -> fp16 m16n8k16 A-fragment order ----------------
__global__ void permA_kernel(const float* __restrict__ hid, uint4* __restrict__ outp) {
    int total = (M_ / 16) * (H2_ / 16) * 32;           // 262144
    for (int i = blockIdx.x * blockDim.x + threadIdx.x; i < total; i += gridDim.x * blockDim.x) {
        int lane = i & 31;
        int kt = (i >> 5) & 63;
        int mt = i >> 11;
        int g = lane >> 2, q = lane & 3;
        int r0 = mt * 16 + g, r1 = r0 + 8;
        int c0 = kt * 16 + 2 * q;
        const float* p0 = hid + (size_t)r0 * H2_ + c0;
        const float* p1 = hid + (size_t)r1 * H2_ + c0;
        float2 v0 = *(const float2*)(p0);
        float2 v1 = *(const float2*)(p1);
        float2 v2 = *(const float2*)(p0 + 8);
        float2 v3 = *(const float2*)(p1 + 8);
        uint4 o;
        o.x = pack2(v0.x, v0.y);
        o.y = pack2(v1.x, v1.y);
        o.z = pack2(v2.x, v2.y);
        o.w = pack2(v3.x, v3.y);
        int mb = mt >> 3, tm = mt & 7, kc = kt >> 3, k16 = kt & 7;
        outp[((((mb * 8 + kc) * 8 + k16) * 8 + tm) << 5) + lane] = o;
    }
}

// ---------------- prep: permute W2 (fp32) -> fp16 m16n8k16 B-fragment order ----------------
__global__ void permB_kernel(const float* __restrict__ W2, uint4* __restrict__ outp) {
    int total = (VPAD2_ / 16) * (H2_ / 16) * 32;
    for (int i = blockIdx.x * blockDim.x + threadIdx.x; i < total; i += gridDim.x * blockDim.x) {
        int lane = i & 31;
        int kt = (i >> 5) & 63;
        int nt2 = i >> 11;
        int g = lane >> 2, q = lane & 3;
        int na = nt2 * 16 + g;
        int nb8 = na + 8;
        int c0 = kt * 16 + 2 * q;
        float2 a0 = make_float2(0.f, 0.f), a1 = a0, b0 = a0, b1 = a0;
        if (na < V_) {
            const float* p = W2 + (size_t)na * H2_ + c0;
            a0 = *(const float2*)(p);
            a1 = *(const float2*)(p + 8);
        }
        if (nb8 < V_) {
            const float* p = W2 + (size_t)nb8 * H2_ + c0;
            b0 = *(const float2*)(p);
            b1 = *(const float2*)(p + 8);
        }
        uint4 o;
        o.x = pack2(a0.x, a0.y);
        o.y = pack2(a1.x, a1.y);
        o.z = pack2(b0.x, b0.y);
        o.w = pack2(b1.x, b1.y);
        int nbk = nt2 >> 4, tn2 = nt2 & 15, kc = kt >> 3, k16 = kt & 7;
        outp[((((nbk * 8 + kc) * 8 + k16) * 16 + tn2) << 5) + lane] = o;
    }
}

// ---------------- K5: logits = hid @ W2^T + b2 (fp16 mma, f16-accumulate + f32 promote) ----------------
__global__ __launch_bounds__(512, 1)
void logits_mma(const uint4* __restrict__ Ap, const uint4* __restrict__ Bp,
                const float* __restrict__ b2, float* __restrict__ out) {
    __shared__ float b2s[BN_];
    extern __shared__ char st[];   // 2 stages x 96KB

    int tid = threadIdx.x, lane = tid & 31, warp = tid >> 5;
    int wm = warp >> 3;   // 0..1  (M)
    int wn = warp & 7;    // 0..7  (N)
    int mb = blockIdx.x, nb = blockIdx.y;

    if (tid < BN_) { int v = nb * BN_ + tid; b2s[tid] = (v < V_) ? b2[v] : 0.f; }

    const uint4* Asrc = Ap + (size_t)mb * 8 * 2048;
    const uint4* Bsrc = Bp + (size_t)nb * 8 * 4096;
    uint32_t stb = smem_u32(st);

    auto prefetch = [&](int c) {
        uint32_t d = stb + (c & 1) * ST_BYTES;
        const uint4* a4 = Asrc + (size_t)c * 2048;
        const uint4* b4 = Bsrc + (size_t)c * 4096;
        #pragma unroll
        for (int i = 0; i < 4; i++)
            cp16(d + (tid + i * 512) * 16, a4 + tid + i * 512);
        uint32_t db = d + ST_A_BYTES;
        #pragma unroll
        for (int i = 0; i < 8; i++)
            cp16(db + (tid + i * 512) * 16, b4 + tid + i * 512);
        asm volatile("cp.async.commit_group;\n" ::: "memory");
    };

    float acc[4][4][4];
    #pragma unroll
    for (int mi = 0; mi < 4; mi++)
        #pragma unroll
        for (int ni = 0; ni < 4; ni++)
            #pragma unroll
            for (int r = 0; r < 4; r++) acc[mi][ni][r] = 0.f;

    prefetch(0);
    prefetch(1);

    for (int c = 0; c < NKT_; c++) {
        if (c < NKT_ - 2)
            asm volatile("cp.async.wait_group 1;\n" ::: "memory");
        else
            asm volatile("cp.async.wait_group 0;\n" ::: "memory");
        __syncthreads();

        const uint4* SA = (const uint4*)(st + (c & 1) * ST_BYTES);     // [k16(8)][tm(8)][lane]
        const uint4* SB = SA + 2048;                                    // [k16(8)][tn2(16)][lane]

        #pragma unroll
        for (int k16 = 0; k16 < 8; k16++) {
            uint4 af[4], bf[2];
            #pragma unroll
            for (int mi = 0; mi < 4; mi++)
                af[mi] = SA[((k16 * 8 + wm * 4 + mi) << 5) + lane];
            #pragma unroll
            for (int n2 = 0; n2 < 2; n2++)
                bf[n2] = SB[((k16 * 16 + wn * 2 + n2) << 5) + lane];
            #pragma unroll
            for (int mi = 0; mi < 4; mi++) {
                #pragma unroll
                for (int n2 = 0; n2 < 2; n2++) {
                    uint32_t d0, d1, e0, e1;
                    mma_f16acc(d0, d1, (const uint32_t*)&af[mi], bf[n2].x, bf[n2].y);
                    mma_f16acc(e0, e1, (const uint32_t*)&af[mi], bf[n2].z, bf[n2].w);
                    float* A0 = acc[mi][n2 * 2];
                    float* A1 = acc[mi][n2 * 2 + 1];
                    float2 p;
                    p = __half22float2(*(__half2*)&d0); A0[0] += p.x; A0[1] += p.y;
                    p = __half22float2(*(__half2*)&d1); A0[2] += p.x; A0[3] += p.y;
                    p = __half22float2(*(__half2*)&e0); A1[0] += p.x; A1[1] += p.y;
                    p = __half22float2(*(__half2*)&e1); A1[2] += p.x; A1[3] += p.y;
                }
            }
        }
        __syncthreads();
        if (c + 2 < NKT_) prefetch(c + 2);
    }

    // epilogue: m = t*B+b ; out[b][t][v]
    int g = lane >> 2, q = lane & 3;
    #pragma unroll
    for (int mi = 0; mi < 4; mi++) {
        int mA = mb * 128 + wm * 64 + mi * 16 + g;
        int mB = mA + 8;
        size_t offA = ((size_t)(mA & 31) * T_ + (size_t)(mA >> 5)) * (size_t)V_;
        size_t offB = ((size_t)(mB & 31) * T_ + (size_t)(mB >> 5)) * (size_t)V_;
        #pragma unroll
        for (int ni = 0; ni < 4; ni++) {
            int cc = wn * 32 + (ni >> 1) * 16 + (ni & 1) * 8 + q * 2;
            int n = nb * BN_ + cc;
            if (n < V_) {
                out[offA + n] = acc[mi][ni][0] + b2s[cc];
                out[offB + n] = acc[mi][ni][2] + b2s[cc];
                if (n + 1 < V_) {
                    out[offA + n + 1] = acc[mi][ni][1] + b2s[cc + 1];
                    out[offB + n + 1] = acc[mi][ni][3] + b2s[cc + 1];
                }
            }
        }
    }
}

// ---------------- launch ----------------
extern "C" void kernel_launch(void* const* d_in, const int* in_sizes, int n_in,
                              void* d_out, int out_size) {
    const float* features = (const float*)d_in[0];
    const int*   captions = (const int*)d_in[1];
    const float* emb      = (const float*)d_in[2];
    const float* W_ih     = (const float*)d_in[3];
    const float* W_hh     = (const float*)d_in[4];
    const float* b_ih     = (const float*)d_in[5];
    const float* b_hh     = (const float*)d_in[6];
    const float* W1       = (const float*)d_in[7];
    const float* b1       = (const float*)d_in[8];
    const float* W2       = (const float*)d_in[9];
    const float* b2       = (const float*)d_in[10];
    float* out = (float*)d_out;

    void *p_base, *p_xg, *p_hs, *p_hid, *p_hidp, *p_w2p;
    cudaGetSymbolAddress(&p_base, g_base);
    cudaGetSymbolAddress(&p_xg,   g_xg);
    cudaGetSymbolAddress(&p_hs,   g_hs);
    cudaGetSymbolAddress(&p_hid,  g_hid);
    cudaGetSymbolAddress(&p_hidp, g_hidp);
    cudaGetSymbolAddress(&p_w2p,  g_w2p);
    float* base = (float*)p_base;
    float* xg   = (float*)p_xg;
    float* hs   = (float*)p_hs;
    float* hid  = (float*)p_hid;

    cudaFuncSetAttribute(logits_mma, cudaFuncAttributeMaxDynamicSharedMemorySize, SMEM_DYN);

    // K0: permute + fp16-round W2
    permB_kernel<<<4096, 256>>>(W2, (uint4*)p_w2p);

    // K1: base gates
    base_kernel<<<B_, 256>>>(features, W_hh, b_ih, b_hh, base);

    // K2: x_gates = gather(emb) @ W_ih^T
    {
        dim3 grid(G4_ / 128, M_ / 128);
        sgemm_tn<<<grid, 256>>>(nullptr, W_ih, nullptr, xg,
                                M_, G4_, E_, captions, emb);
    }

    // K3: LSTM scan
    lstm_scan<<<128, 128>>>(xg, base, hs);

    // K4: hid = hs @ W1^T + b1 (fp32)
    {
        dim3 grid(H2_ / 128, M_ / 128);
        sgemm_tn<<<grid, 256>>>(hs, W1, b1, hid,
                                M_, H2_, H_, nullptr, nullptr);
    }

    // K4b: permute + fp16-round hid
    permA_kernel<<<512, 256>>>(hid, (uint4*)p_hidp);

    // K5: logits via fp16 mma (f16 accumulate + f32 promote)
    {
        dim3 grid(M_ / BM_, VPAD2_ / BN_);   // (16, 197)
        logits_mma<<<grid, 512, SMEM_DYN>>>((const uint4*)p_hidp, (const uint4*)p_w2p, b2, out);
    }
}

// round 12
// speedup vs baseline: 1.3287x; 1.3287x over previous
#include <cuda_runtime.h>
#include <cuda_fp16.h>
#include <cstdint>

// Problem constants
#define B_  32
#define T_  64
#define V_  50257
#define E_  256
#define H_  512
#define G4_ 2048   // 4*H
#define H2_ 1024   // 2*H
#define M_  2048   // T*B
#define VPAD2_ 50432  // 197*256

// mma tiling: CTA 128x256, 512 threads (16 warps 2x8), warp tile 64x32, BK=128
#define BM_ 128
#define BN_ 256
#define ST_A_BYTES 32768          // 128*128*2
#define ST_B_BYTES 65536          // 256*128*2
#define ST_BYTES   98304
#define SMEM_DYN   (2 * ST_BYTES) // 196608

// ---------------- scratch (device globals; no allocation allowed) ----------------
__device__ float g_base[B_ * G4_];
__device__ float g_xg[M_ * G4_];
__device__ float g_hs[M_ * H_];
__device__ __align__(16) __half g_embp[(size_t)M_ * E_];            // gathered emb A-frags (K2)
__device__ __align__(16) __half g_wihp[(size_t)G4_ * E_];           // W_ih B-frags (K2)
__device__ __align__(16) __half g_hsp[(size_t)M_ * H_];             // hs A-frags (K4)
__device__ __align__(16) __half g_w1p[(size_t)H2_ * H_];            // W1 B-frags (K4)
__device__ __align__(16) __half g_hidp[(size_t)M_ * H2_];           // hid A-frags (K5), written by K4
__device__ __align__(16) __half g_w2p[(size_t)VPAD2_ * H2_];        // W2 B-frags (K5)

// ---------------- helpers ----------------
__device__ __forceinline__ void mma_f16(float* d, const uint32_t* a, uint32_t b0, uint32_t b1) {
    asm volatile(
        "mma.sync.aligned.m16n8k16.row.col.f32.f16.f16.f32 "
        "{%0,%1,%2,%3}, {%4,%5,%6,%7}, {%8,%9}, {%0,%1,%2,%3};\n"
        : "+f"(d[0]), "+f"(d[1]), "+f"(d[2]), "+f"(d[3])
        : "r"(a[0]), "r"(a[1]), "r"(a[2]), "r"(a[3]), "r"(b0), "r"(b1));
}

__device__ __forceinline__ float sigf(float x) {
    return __fdividef(1.f, 1.f + __expf(-x));
}
__device__ __forceinline__ float ftanh(float x) {
    float e = __expf(2.f * x);
    return 1.f - __fdividef(2.f, e + 1.f);
}

__device__ __forceinline__ uint32_t smem_u32(const void* p) {
    return (uint32_t)__cvta_generic_to_shared(p);
}

__device__ __forceinline__ void cp16(uint32_t dst, const void* src) {
    asm volatile("cp.async.cg.shared.global [%0], [%1], 16;\n"
                 :: "r"(dst), "l"(src) : "memory");
}

__device__ __forceinline__ uint32_t pack2(float lo, float hi) {
    __half2 h = __floats2half2_rn(lo, hi);
    return *(uint32_t*)&h;
}

// ---------------- K1: base gates = features @ W_hh^T + b_ih + b_hh ----------------
__global__ void base_kernel(const float* __restrict__ feat,
                            const float* __restrict__ W_hh,
                            const float* __restrict__ b_ih,
                            const float* __restrict__ b_hh,
                            float* __restrict__ base) {
    __shared__ float4 f4[H_ / 4];
    int b = blockIdx.x;
    if (threadIdx.x < H_ / 4)
        f4[threadIdx.x] = ((const float4*)(feat + (size_t)b * H_))[threadIdx.x];
    __syncthreads();
    for (int g = threadIdx.x; g < G4_; g += blockDim.x) {
        const float4* w4 = (const float4*)(W_hh + (size_t)g * H_);
        float s = 0.f;
        #pragma unroll 8
        for (int k = 0; k < H_ / 4; k++) {
            float4 w = w4[k], f = f4[k];
            s += w.x * f.x + w.y * f.y + w.z * f.z + w.w * f.w;
        }
        base[b * G4_ + g] = s + b_ih[g] + b_hh[g];
    }
}

// ---------------- K3: LSTM scan (depth-8 prefetch) ----------------
__global__ void lstm_scan(const float* __restrict__ xg,
                          const float* __restrict__ base,
                          float* __restrict__ hs) {
    int idx = blockIdx.x * blockDim.x + threadIdx.x;
    int b = idx >> 9, h = idx & 511;
    float bi = base[b * G4_ + h];
    float bff = base[b * G4_ + H_ + h];
    float bg = base[b * G4_ + 2 * H_ + h];
    float bo = base[b * G4_ + 3 * H_ + h];

    const float* xr = xg + (size_t)b * G4_ + h;
    const size_t step = (size_t)B_ * G4_;

    float4 pf[8];
    #pragma unroll
    for (int j = 0; j < 8; j++) {
        const float* p = xr + (size_t)j * step;
        pf[j] = make_float4(p[0], p[H_], p[2 * H_], p[3 * H_]);
    }

    float c = 0.f;
    float* hp = hs + (size_t)b * H_ + h;
    #pragma unroll 8
    for (int t = 0; t < T_; t++) {
        float4 cur = pf[t & 7];
        if (t + 8 < T_) {
            const float* p = xr + (size_t)(t + 8) * step;
            pf[t & 7] = make_float4(p[0], p[H_], p[2 * H_], p[3 * H_]);
        }
        float i = sigf(cur.x + bi);
        float f = sigf(cur.y + bff);
        float g = ftanh(cur.z + bg);
        float o = sigf(cur.w + bo);
        c = f * c + i * g;
        hp[(size_t)t * B_ * H_] = o * ftanh(c);
    }
}

// ---------------- generic A-perm: fp32 [M x K] -> fp16 m16n8k16 A-fragments ----------------
__global__ void permA_g(const float* __restrict__ src, uint4* __restrict__ outp,
                        int M, int K, int kcnt) {
    int ktcnt = K >> 4;
    int total = (M >> 4) * ktcnt * 32;
    for (int i = blockIdx.x * blockDim.x + threadIdx.x; i < total; i += gridDim.x * blockDim.x) {
        int lane = i & 31;
        int kt = (i >> 5) % ktcnt;
        int mt = (i >> 5) / ktcnt;
        int g = lane >> 2, q = lane & 3;
        int r0 = mt * 16 + g, r1 = r0 + 8;
        int c0 = kt * 16 + 2 * q;
        const float* p0 = src + (size_t)r0 * K + c0;
        const float* p1 = src + (size_t)r1 * K + c0;
        float2 v0 = *(const float2*)(p0);
        float2 v1 = *(const float2*)(p1);
        float2 v2 = *(const float2*)(p0 + 8);
        float2 v3 = *(const float2*)(p1 + 8);
        uint4 o;
        o.x = pack2(v0.x, v0.y);
        o.y = pack2(v1.x, v1.y);
        o.z = pack2(v2.x, v2.y);
        o.w = pack2(v3.x, v3.y);
        int mb = mt >> 3, tm = mt & 7, kc = kt >> 3, k16 = kt & 7;
        outp[((((mb * kcnt + kc) * 8 + k16) * 8 + tm) << 5) + lane] = o;
    }
}

// ---------------- gathered emb A-perm (K2): rows are emb[tok(m)] ----------------
__global__ void permA_emb(const float* __restrict__ emb, const int* __restrict__ captions,
                          uint4* __restrict__ outp) {
    const int K = E_, ktcnt = E_ / 16, kcnt = E_ / 128;   // 16, 2
    int total = (M_ / 16) * ktcnt * 32;
    for (int i = blockIdx.x * blockDim.x + threadIdx.x; i < total; i += gridDim.x * blockDim.x) {
        int lane = i & 31;
        int kt = (i >> 5) % ktcnt;
        int mt = (i >> 5) / ktcnt;
        int g = lane >> 2, q = lane & 3;
        int m0 = mt * 16 + g, m1 = m0 + 8;
        int c0 = kt * 16 + 2 * q;
        int b0 = m0 & 31, t0 = m0 >> 5;
        int b1 = m1 & 31, t1 = m1 >> 5;
        int tok0 = captions[b0 * T_ + (t0 ? t0 - 1 : 0)];
        int tok1 = captions[b1 * T_ + (t1 ? t1 - 1 : 0)];
        const float* p0 = emb + (size_t)tok0 * K + c0;
        const float* p1 = emb + (size_t)tok1 * K + c0;
        float2 v0 = *(const float2*)(p0);
        float2 v1 = *(const float2*)(p1);
        float2 v2 = *(const float2*)(p0 + 8);
        float2 v3 = *(const float2*)(p1 + 8);
        uint4 o;
        o.x = pack2(v0.x, v0.y);
        o.y = pack2(v1.x, v1.y);
        o.z = pack2(v2.x, v2.y);
        o.w = pack2(v3.x, v3.y);
        int mb = mt >> 3, tm = mt & 7, kc = kt >> 3, k16 = kt & 7;
        outp[((((mb * kcnt + kc) * 8 + k16) * 8 + tm) << 5) + lane] = o;
    }
}

// ---------------- generic B-perm: fp32 [N x K] -> fp16 m16n8k16 B-fragments ----------------
__global__ void permB_g(const float* __restrict__ src, uint4* __restrict__ outp,
                        int K, int kcnt, int Npad, int nValid) {
    int ktcnt = K >> 4;
    int total = (Npad >> 4) * ktcnt * 32;
    for (int i = blockIdx.x * blockDim.x + threadIdx.x; i < total; i += gridDim.x * blockDim.x) {
        int lane = i & 31;
        int kt = (i >> 5) % ktcnt;
        int nt2 = (i >> 5) / ktcnt;
        int g = lane >> 2, q = lane & 3;
        int na = nt2 * 16 + g;
        int nb8 = na + 8;
        int c0 = kt * 16 + 2 * q;
        float2 a0 = make_float2(0.f, 0.f), a1 = a0, b0 = a0, b1 = a0;
        if (na < nValid) {
            const float* p = src + (size_t)na * K + c0;
            a0 = *(const float2*)(p);
            a1 = *(const float2*)(p + 8);
        }
        if (nb8 < nValid) {
            const float* p = src + (size_t)nb8 * K + c0;
            b0 = *(const float2*)(p);
            b1 = *(const float2*)(p + 8);
        }
        uint4 o;
        o.x = pack2(a0.x, a0.y);
        o.y = pack2(a1.x, a1.y);
        o.z = pack2(b0.x, b0.y);
        o.w = pack2(b1.x, b1.y);
        int nbk = nt2 >> 4, tn2 = nt2 & 15, kc = kt >> 3, k16 = kt & 7;
        outp[((((nbk * kcnt + kc) * 8 + k16) * 16 + tn2) << 5) + lane] = o;
    }
}

// ---------------- shared fp16-mma mainloop (CTA 128x256, BK=128 chunks) ----------------
__device__ __forceinline__ void gemm_mainloop(const uint4* __restrict__ Asrc,
                                              const uint4* __restrict__ Bsrc,
                                              int nkt, char* st,
                                              int tid, int lane, int wm, int wn,
                                              float acc[4][4][4]) {
    uint32_t stb = smem_u32(st);
    auto prefetch = [&](int c) {
        uint32_t d = stb + (c & 1) * ST_BYTES;
        const uint4* a4 = Asrc + (size_t)c * 2048;
        const uint4* b4 = Bsrc + (size_t)c * 4096;
        #pragma unroll
        for (int i = 0; i < 4; i++)
            cp16(d + (tid + i * 512) * 16, a4 + tid + i * 512);
        uint32_t db = d + ST_A_BYTES;
        #pragma unroll
        for (int i = 0; i < 8; i++)
            cp16(db + (tid + i * 512) * 16, b4 + tid + i * 512);
        asm volatile("cp.async.commit_group;\n" ::: "memory");
    };

    #pragma unroll
    for (int mi = 0; mi < 4; mi++)
        #pragma unroll
        for (int ni = 0; ni < 4; ni++)
            #pragma unroll
            for (int r = 0; r < 4; r++) acc[mi][ni][r] = 0.f;

    prefetch(0);
    prefetch(1);

    for (int c = 0; c < nkt; c++) {
        if (c < nkt - 2)
            asm volatile("cp.async.wait_group 1;\n" ::: "memory");
        else
            asm volatile("cp.async.wait_group 0;\n" ::: "memory");
        __syncthreads();

        const uint4* SA = (const uint4*)(st + (c & 1) * ST_BYTES);     // [k16(8)][tm(8)][lane]
        const uint4* SB = SA + 2048;                                    // [k16(8)][tn2(16)][lane]

        #pragma unroll
        for (int k16 = 0; k16 < 8; k16++) {
            uint4 af[4], bf[2];
            #pragma unroll
            for (int mi = 0; mi < 4; mi++)
                af[mi] = SA[((k16 * 8 + wm * 4 + mi) << 5) + lane];
            #pragma unroll
            for (int n2 = 0; n2 < 2; n2++)
                bf[n2] = SB[((k16 * 16 + wn * 2 + n2) << 5) + lane];
            #pragma unroll
            for (int mi = 0; mi < 4; mi++)
                #pragma unroll
                for (int n2 = 0; n2 < 2; n2++) {
                    mma_f16(acc[mi][n2 * 2],     (const uint32_t*)&af[mi], bf[n2].x, bf[n2].y);
                    mma_f16(acc[mi][n2 * 2 + 1], (const uint32_t*)&af[mi], bf[n2].z, bf[n2].w);
                }
        }
        __syncthreads();
        if (c + 2 < nkt) prefetch(c + 2);
    }
}

// ---------------- K2: xg = gathered_emb @ W_ih^T (fp16 mma, fp32 out) ----------------
__global__ __launch_bounds__(512, 1)
void gemm_xg(const uint4* __restrict__ Ap, const uint4* __restrict__ Bp,
             float* __restrict__ xg) {
    extern __shared__ char st[];
    int tid = threadIdx.x, lane = tid & 31, warp = tid >> 5;
    int wm = warp >> 3, wn = warp & 7;
    int mb = blockIdx.x, nb = blockIdx.y;

    float acc[4][4][4];
    gemm_mainloop(Ap + (size_t)mb * 2 * 2048, Bp + (size_t)nb * 2 * 4096, 2,
                  st, tid, lane, wm, wn, acc);

    int g = lane >> 2, q = lane & 3;
    #pragma unroll
    for (int mi = 0; mi < 4; mi++) {
        int mA = mb * 128 + wm * 64 + mi * 16 + g;
        int mB = mA + 8;
        #pragma unroll
        for (int ni = 0; ni < 4; ni++) {
            int cc = wn * 32 + (ni >> 1) * 16 + (ni & 1) * 8 + q * 2;
            int n = nb * BN_ + cc;
            xg[(size_t)mA * G4_ + n]     = acc[mi][ni][0];
            xg[(size_t)mA * G4_ + n + 1] = acc[mi][ni][1];
            xg[(size_t)mB * G4_ + n]     = acc[mi][ni][2];
            xg[(size_t)mB * G4_ + n + 1] = acc[mi][ni][3];
        }
    }
}

// ---------------- K4: hid = hs @ W1^T + b1, epilogue writes K5 A-fragments directly ----------------
__global__ __launch_bounds__(512, 1)
void gemm_hid(const uint4* __restrict__ Ap, const uint4* __restrict__ Bp,
              const float* __restrict__ b1, uint4* __restrict__ outp) {
    __shared__ float b1s[BN_];
    extern __shared__ char st[];
    int tid = threadIdx.x, lane = tid & 31, warp = tid >> 5;
    int wm = warp >> 3, wn = warp & 7;
    int mb = blockIdx.x, nb = blockIdx.y;

    if (tid < BN_) b1s[tid] = b1[nb * BN_ + tid];

    float acc[4][4][4];
    gemm_mainloop(Ap + (size_t)mb * 4 * 2048, Bp + (size_t)nb * 4 * 4096, 4,
                  st, tid, lane, wm, wn, acc);

    int q = lane & 3;
    #pragma unroll
    for (int mi = 0; mi < 4; mi++) {
        int mA = mb * 128 + wm * 64 + mi * 16;   // tile base row
        int mb5 = mA >> 7, tm = (mA >> 4) & 7;
        #pragma unroll
        for (int j = 0; j < 2; j++) {
            int kt = nb * 16 + wn * 2 + j;       // n16 index = hid k16 index
            int kc = kt >> 3, k16 = kt & 7;
            int c = wn * 32 + j * 16 + 2 * q;    // local bias col
            float* L = acc[mi][2 * j];
            float* Hh = acc[mi][2 * j + 1];
            uint4 o;
            o.x = pack2(L[0] + b1s[c],      L[1] + b1s[c + 1]);
            o.y = pack2(L[2] + b1s[c],      L[3] + b1s[c + 1]);
            o.z = pack2(Hh[0] + b1s[c + 8], Hh[1] + b1s[c + 9]);
            o.w = pack2(Hh[2] + b1s[c + 8], Hh[3] + b1s[c + 9]);
            outp[((((mb5 * 8 + kc) * 8 + k16) * 8 + tm) << 5) + lane] = o;
        }
    }
}

// ---------------- K5: logits = hid @ W2^T + b2 ----------------
__global__ __launch_bounds__(512, 1)
void logits_mma(const uint4* __restrict__ Ap, const uint4* __restrict__ Bp,
                const float* __restrict__ b2, float* __restrict__ out) {
    __shared__ float b2s[BN_];
    extern __shared__ char st[];
    int tid = threadIdx.x, lane = tid & 31, warp = tid >> 5;
    int wm = warp >> 3, wn = warp & 7;
    int mb = blockIdx.x, nb = blockIdx.y;

    if (tid < BN_) { int v = nb * BN_ + tid; b2s[tid] = (v < V_) ? b2[v] : 0.f; }

    float acc[4][4][4];
    gemm_mainloop(Ap + (size_t)mb * 8 * 2048, Bp + (size_t)nb * 8 * 4096, 8,
                  st, tid, lane, wm, wn, acc);

    // epilogue: m = t*B+b ; out[b][t][v]
    int g = lane >> 2, q = lane & 3;
    #pragma unroll
    for (int mi = 0; mi < 4; mi++) {
        int mA = mb * 128 + wm * 64 + mi * 16 + g;
        int mB = mA + 8;
        size_t offA = ((size_t)(mA & 31) * T_ + (size_t)(mA >> 5)) * (size_t)V_;
        size_t offB = ((size_t)(mB & 31) * T_ + (size_t)(mB >> 5)) * (size_t)V_;
        #pragma unroll
        for (int ni = 0; ni < 4; ni++) {
            int cc = wn * 32 + (ni >> 1) * 16 + (ni & 1) * 8 + q * 2;
            int n = nb * BN_ + cc;
            if (n < V_) {
                out[offA + n] = acc[mi][ni][0] + b2s[cc];
                out[offB + n] = acc[mi][ni][2] + b2s[cc];
                if (n + 1 < V_) {
                    out[offA + n + 1] = acc[mi][ni][1] + b2s[cc + 1];
                    out[offB + n + 1] = acc[mi][ni][3] + b2s[cc + 1];
                }
            }
        }
    }
}

// ---------------- launch ----------------
extern "C" void kernel_launch(void* const* d_in, const int* in_sizes, int n_in,
                              void* d_out, int out_size) {
    const float* features = (const float*)d_in[0];
    const int*   captions = (const int*)d_in[1];
    const float* emb      = (const float*)d_in[2];
    const float* W_ih     = (const float*)d_in[3];
    const float* W_hh     = (const float*)d_in[4];
    const float* b_ih     = (const float*)d_in[5];
    const float* b_hh     = (const float*)d_in[6];
    const float* W1       = (const float*)d_in[7];
    const float* b1       = (const float*)d_in[8];
    const float* W2       = (const float*)d_in[9];
    const float* b2       = (const float*)d_in[10];
    float* out = (float*)d_out;

    void *p_base, *p_xg, *p_hs, *p_embp, *p_wihp, *p_hsp, *p_w1p, *p_hidp, *p_w2p;
    cudaGetSymbolAddress(&p_base, g_base);
    cudaGetSymbolAddress(&p_xg,   g_xg);
    cudaGetSymbolAddress(&p_hs,   g_hs);
    cudaGetSymbolAddress(&p_embp, g_embp);
    cudaGetSymbolAddress(&p_wihp, g_wihp);
    cudaGetSymbolAddress(&p_hsp,  g_hsp);
    cudaGetSymbolAddress(&p_w1p,  g_w1p);
    cudaGetSymbolAddress(&p_hidp, g_hidp);
    cudaGetSymbolAddress(&p_w2p,  g_w2p);
    float* base = (float*)p_base;
    float* xg   = (float*)p_xg;
    float* hs   = (float*)p_hs;

    cudaFuncSetAttribute(gemm_xg,    cudaFuncAttributeMaxDynamicSharedMemorySize, SMEM_DYN);
    cudaFuncSetAttribute(gemm_hid,   cudaFuncAttributeMaxDynamicSharedMemorySize, SMEM_DYN);
    cudaFuncSetAttribute(logits_mma, cudaFuncAttributeMaxDynamicSharedMemorySize, SMEM_DYN);

    // prep: W2 B-frags (dominant prep; K=1024, kcnt=8)
    permB_g<<<4096, 256>>>(W2, (uint4*)p_w2p, H2_, 8, VPAD2_, V_);
    // prep: W_ih B-frags (K=256, kcnt=2, N=2048)
    permB_g<<<256, 256>>>(W_ih, (uint4*)p_wihp, E_, 2, G4_, G4_);
    // prep: W1 B-frags (K=512, kcnt=4, N=1024)
    permB_g<<<256, 256>>>(W1, (uint4*)p_w1p, H_, 4, H2_, H2_);
    // prep: gathered emb A-frags
    permA_emb<<<256, 256>>>(emb, captions, (uint4*)p_embp);

    // K1: base gates
    base_kernel<<<B_, 256>>>(features, W_hh, b_ih, b_hh, base);

    // K2: xg = emb_gathered @ W_ih^T  (fp16 mma)
    {
        dim3 grid(M_ / BM_, G4_ / BN_);   // (16, 8)
        gemm_xg<<<grid, 512, SMEM_DYN>>>((const uint4*)p_embp, (const uint4*)p_wihp, xg);
    }

    // K3: LSTM scan
    lstm_scan<<<128, 128>>>(xg, base, hs);

    // prep: hs A-frags (K=512, kcnt=4)
    permA_g<<<256, 256>>>(hs, (uint4*)p_hsp, M_, H_, 4);

    // K4: hid = hs @ W1^T + b1 -> writes K5 A-fragments directly (fp16)
    {
        dim3 grid(M_ / BM_, H2_ / BN_);   // (16, 4)
        gemm_hid<<<grid, 512, SMEM_DYN>>>((const uint4*)p_hsp, (const uint4*)p_w1p, b1,
                                          (uint4*)p_hidp);
    }

    // K5: logits
    {
        dim3 grid(M_ / BM_, VPAD2_ / BN_);   // (16, 197)
        logits_mma<<<grid, 512, SMEM_DYN>>>((const uint4*)p_hidp, (const uint4*)p_w2p, b2, out);
    }
}

// round 13
// speedup vs baseline: 1.3447x; 1.0120x over previous
#include <cuda_runtime.h>
#include <cuda_fp16.h>
#include <cstdint>

// Problem constants
#define B_  32
#define T_  64
#define V_  50257
#define E_  256
#define H_  512
#define G4_ 2048   // 4*H
#define H2_ 1024   // 2*H
#define M_  2048   // T*B
#define VPAD2_ 50432  // 197*256

// mma tiling: CTA 128x256, 512 threads (16 warps 2x8), warp tile 64x32, BK=128
#define BM_ 128
#define BN_ 256
#define ST_A_BYTES 32768          // 128*128*2
#define ST_B_BYTES 65536          // 256*128*2
#define ST_BYTES   98304
#define SMEM_DYN   (2 * ST_BYTES) // 196608

// ---------------- scratch (device globals; no allocation allowed) ----------------
__device__ float g_base[B_ * G4_];
__device__ float g_xg[M_ * G4_];
__device__ float g_hs[M_ * H_];
__device__ __align__(16) __half g_embp[(size_t)M_ * E_];            // gathered emb A-frags (K2)
__device__ __align__(16) __half g_wihp[(size_t)G4_ * E_];           // W_ih B-frags (K2)
__device__ __align__(16) __half g_hsp[(size_t)M_ * H_];             // hs A-frags (K4)
__device__ __align__(16) __half g_w1p[(size_t)H2_ * H_];            // W1 B-frags (K4)
__device__ __align__(16) __half g_hidp[(size_t)M_ * H2_];           // hid A-frags (K5), written by K4
__device__ __align__(16) __half g_w2p[(size_t)VPAD2_ * H2_];        // W2 B-frags (K5)

// ---------------- helpers ----------------
__device__ __forceinline__ void mma_f16(float* d, const uint32_t* a, uint32_t b0, uint32_t b1) {
    asm volatile(
        "mma.sync.aligned.m16n8k16.row.col.f32.f16.f16.f32 "
        "{%0,%1,%2,%3}, {%4,%5,%6,%7}, {%8,%9}, {%0,%1,%2,%3};\n"
        : "+f"(d[0]), "+f"(d[1]), "+f"(d[2]), "+f"(d[3])
        : "r"(a[0]), "r"(a[1]), "r"(a[2]), "r"(a[3]), "r"(b0), "r"(b1));
}

__device__ __forceinline__ float sigf(float x) {
    return __fdividef(1.f, 1.f + __expf(-x));
}
__device__ __forceinline__ float ftanh(float x) {
    float e = __expf(2.f * x);
    return 1.f - __fdividef(2.f, e + 1.f);
}

__device__ __forceinline__ uint32_t smem_u32(const void* p) {
    return (uint32_t)__cvta_generic_to_shared(p);
}

__device__ __forceinline__ void cp16(uint32_t dst, const void* src) {
    asm volatile("cp.async.cg.shared.global [%0], [%1], 16;\n"
                 :: "r"(dst), "l"(src) : "memory");
}

__device__ __forceinline__ uint32_t pack2(float lo, float hi) {
    __half2 h = __floats2half2_rn(lo, hi);
    return *(uint32_t*)&h;
}

// ---------------- K1: base gates = features @ W_hh^T + b_ih + b_hh ----------------
__global__ void base_kernel(const float* __restrict__ feat,
                            const float* __restrict__ W_hh,
                            const float* __restrict__ b_ih,
                            const float* __restrict__ b_hh,
                            float* __restrict__ base) {
    __shared__ float4 f4[H_ / 4];
    int b = blockIdx.x;
    if (threadIdx.x < H_ / 4)
        f4[threadIdx.x] = ((const float4*)(feat + (size_t)b * H_))[threadIdx.x];
    __syncthreads();
    for (int g = threadIdx.x; g < G4_; g += blockDim.x) {
        const float4* w4 = (const float4*)(W_hh + (size_t)g * H_);
        float s = 0.f;
        #pragma unroll 8
        for (int k = 0; k < H_ / 4; k++) {
            float4 w = w4[k], f = f4[k];
            s += w.x * f.x + w.y * f.y + w.z * f.z + w.w * f.w;
        }
        base[b * G4_ + g] = s + b_ih[g] + b_hh[g];
    }
}

// ---------------- K3: LSTM scan (depth-8 prefetch) ----------------
__global__ void lstm_scan(const float* __restrict__ xg,
                          const float* __restrict__ base,
                          float* __restrict__ hs) {
    int idx = blockIdx.x * blockDim.x + threadIdx.x;
    int b = idx >> 9, h = idx & 511;
    float bi = base[b * G4_ + h];
    float bff = base[b * G4_ + H_ + h];
    float bg = base[b * G4_ + 2 * H_ + h];
    float bo = base[b * G4_ + 3 * H_ + h];

    const float* xr = xg + (size_t)b * G4_ + h;
    const size_t step = (size_t)B_ * G4_;

    float4 pf[8];
    #pragma unroll
    for (int j = 0; j < 8; j++) {
        const float* p = xr + (size_t)j * step;
        pf[j] = make_float4(p[0], p[H_], p[2 * H_], p[3 * H_]);
    }

    float c = 0.f;
    float* hp = hs + (size_t)b * H_ + h;
    #pragma unroll 8
    for (int t = 0; t < T_; t++) {
        float4 cur = pf[t & 7];
        if (t + 8 < T_) {
            const float* p = xr + (size_t)(t + 8) * step;
            pf[t & 7] = make_float4(p[0], p[H_], p[2 * H_], p[3 * H_]);
        }
        float i = sigf(cur.x + bi);
        float f = sigf(cur.y + bff);
        float g = ftanh(cur.z + bg);
        float o = sigf(cur.w + bo);
        c = f * c + i * g;
        hp[(size_t)t * B_ * H_] = o * ftanh(c);
    }
}

// ---------------- generic A-perm: fp32 [M x K] -> fp16 m16n8k16 A-fragments ----------------
__global__ void permA_g(const float* __restrict__ src, uint4* __restrict__ outp,
                        int M, int K, int kcnt) {
    int ktcnt = K >> 4;
    int total = (M >> 4) * ktcnt * 32;
    for (int i = blockIdx.x * blockDim.x + threadIdx.x; i < total; i += gridDim.x * blockDim.x) {
        int lane = i & 31;
        int kt = (i >> 5) % ktcnt;
        int mt = (i >> 5) / ktcnt;
        int g = lane >> 2, q = lane & 3;
        int r0 = mt * 16 + g, r1 = r0 + 8;
        int c0 = kt * 16 + 2 * q;
        const float* p0 = src + (size_t)r0 * K + c0;
        const float* p1 = src + (size_t)r1 * K + c0;
        float2 v0 = *(const float2*)(p0);
        float2 v1 = *(const float2*)(p1);
        float2 v2 = *(const float2*)(p0 + 8);
        float2 v3 = *(const float2*)(p1 + 8);
        uint4 o;
        o.x = pack2(v0.x, v0.y);
        o.y = pack2(v1.x, v1.y);
        o.z = pack2(v2.x, v2.y);
        o.w = pack2(v3.x, v3.y);
        int mb = mt >> 3, tm = mt & 7, kc = kt >> 3, k16 = kt & 7;
        outp[((((mb * kcnt + kc) * 8 + k16) * 8 + tm) << 5) + lane] = o;
    }
}

// ---------------- gathered emb A-perm (K2): rows are emb[tok(m)] ----------------
__global__ void permA_emb(const float* __restrict__ emb, const int* __restrict__ captions,
                          uint4* __restrict__ outp) {
    const int K = E_, ktcnt = E_ / 16, kcnt = E_ / 128;   // 16, 2
    int total = (M_ / 16) * ktcnt * 32;
    for (int i = blockIdx.x * blockDim.x + threadIdx.x; i < total; i += gridDim.x * blockDim.x) {
        int lane = i & 31;
        int kt = (i >> 5) % ktcnt;
        int mt = (i >> 5) / ktcnt;
        int g = lane >> 2, q = lane & 3;
        int m0 = mt * 16 + g, m1 = m0 + 8;
        int c0 = kt * 16 + 2 * q;
        int b0 = m0 & 31, t0 = m0 >> 5;
        int b1 = m1 & 31, t1 = m1 >> 5;
        int tok0 = captions[b0 * T_ + (t0 ? t0 - 1 : 0)];
        int tok1 = captions[b1 * T_ + (t1 ? t1 - 1 : 0)];
        const float* p0 = emb + (size_t)tok0 * K + c0;
        const float* p1 = emb + (size_t)tok1 * K + c0;
        float2 v0 = *(const float2*)(p0);
        float2 v1 = *(const float2*)(p1);
        float2 v2 = *(const float2*)(p0 + 8);
        float2 v3 = *(const float2*)(p1 + 8);
        uint4 o;
        o.x = pack2(v0.x, v0.y);
        o.y = pack2(v1.x, v1.y);
        o.z = pack2(v2.x, v2.y);
        o.w = pack2(v3.x, v3.y);
        int mb = mt >> 3, tm = mt & 7, kc = kt >> 3, k16 = kt & 7;
        outp[((((mb * kcnt + kc) * 8 + k16) * 8 + tm) << 5) + lane] = o;
    }
}

// ---------------- generic B-perm: fp32 [N x K] -> fp16 m16n8k16 B-fragments ----------------
__global__ void permB_g(const float* __restrict__ src, uint4* __restrict__ outp,
                        int K, int kcnt, int Npad, int nValid) {
    int ktcnt = K >> 4;
    int total = (Npad >> 4) * ktcnt * 32;
    for (int i = blockIdx.x * blockDim.x + threadIdx.x; i < total; i += gridDim.x * blockDim.x) {
        int lane = i & 31;
        int kt = (i >> 5) % ktcnt;
        int nt2 = (i >> 5) / ktcnt;
        int g = lane >> 2, q = lane & 3;
        int na = nt2 * 16 + g;
        int nb8 = na + 8;
        int c0 = kt * 16 + 2 * q;
        float2 a0 = make_float2(0.f, 0.f), a1 = a0, b0 = a0, b1 = a0;
        if (na < nValid) {
            const float* p = src + (size_t)na * K + c0;
            a0 = *(const float2*)(p);
            a1 = *(const float2*)(p + 8);
        }
        if (nb8 < nValid) {
            const float* p = src + (size_t)nb8 * K + c0;
            b0 = *(const float2*)(p);
            b1 = *(const float2*)(p + 8);
        }
        uint4 o;
        o.x = pack2(a0.x, a0.y);
        o.y = pack2(a1.x, a1.y);
        o.z = pack2(b0.x, b0.y);
        o.w = pack2(b1.x, b1.y);
        int nbk = nt2 >> 4, tn2 = nt2 & 15, kc = kt >> 3, k16 = kt & 7;
        outp[((((nbk * kcnt + kc) * 8 + k16) * 16 + tn2) << 5) + lane] = o;
    }
}

// ---------------- shared fp16-mma mainloop (CTA 128x256, BK=128 chunks) ----------------
__device__ __forceinline__ void gemm_mainloop(const uint4* __restrict__ Asrc,
                                              const uint4* __restrict__ Bsrc,
                                              int nkt, char* st,
                                              int tid, int lane, int wm, int wn,
                                              float acc[4][4][4]) {
    uint32_t stb = smem_u32(st);
    auto prefetch = [&](int c) {
        uint32_t d = stb + (c & 1) * ST_BYTES;
        const uint4* a4 = Asrc + (size_t)c * 2048;
        const uint4* b4 = Bsrc + (size_t)c * 4096;
        #pragma unroll
        for (int i = 0; i < 4; i++)
            cp16(d + (tid + i * 512) * 16, a4 + tid + i * 512);
        uint32_t db = d + ST_A_BYTES;
        #pragma unroll
        for (int i = 0; i < 8; i++)
            cp16(db + (tid + i * 512) * 16, b4 + tid + i * 512);
        asm volatile("cp.async.commit_group;\n" ::: "memory");
    };

    #pragma unroll
    for (int mi = 0; mi < 4; mi++)
        #pragma unroll
        for (int ni = 0; ni < 4; ni++)
            #pragma unroll
            for (int r = 0; r < 4; r++) acc[mi][ni][r] = 0.f;

    prefetch(0);
    prefetch(1);

    for (int c = 0; c < nkt; c++) {
        if (c < nkt - 2)
            asm volatile("cp.async.wait_group 1;\n" ::: "memory");
        else
            asm volatile("cp.async.wait_group 0;\n" ::: "memory");
        __syncthreads();

        const uint4* SA = (const uint4*)(st + (c & 1) * ST_BYTES);     // [k16(8)][tm(8)][lane]
        const uint4* SB = SA + 2048;                                    // [k16(8)][tn2(16)][lane]

        #pragma unroll
        for (int k16 = 0; k16 < 8; k16++) {
            uint4 af[4], bf[2];
            #pragma unroll
            for (int mi = 0; mi < 4; mi++)
                af[mi] = SA[((k16 * 8 + wm * 4 + mi) << 5) + lane];
            #pragma unroll
            for (int n2 = 0; n2 < 2; n2++)
                bf[n2] = SB[((k16 * 16 + wn * 2 + n2) << 5) + lane];
            #pragma unroll
            for (int mi = 0; mi < 4; mi++)
                #pragma unroll
                for (int n2 = 0; n2 < 2; n2++) {
                    mma_f16(acc[mi][n2 * 2],     (const uint32_t*)&af[mi], bf[n2].x, bf[n2].y);
                    mma_f16(acc[mi][n2 * 2 + 1], (const uint32_t*)&af[mi], bf[n2].z, bf[n2].w);
                }
        }
        __syncthreads();
        if (c + 2 < nkt) prefetch(c + 2);
    }
}

// ---------------- K2: xg = gathered_emb @ W_ih^T (fp16 mma, fp32 out) ----------------
__global__ __launch_bounds__(512, 1)
void gemm_xg(const uint4* __restrict__ Ap, const uint4* __restrict__ Bp,
             float* __restrict__ xg) {
    extern __shared__ char st[];
    int tid = threadIdx.x, lane = tid & 31, warp = tid >> 5;
    int wm = warp >> 3, wn = warp & 7;
    int mb = blockIdx.x, nb = blockIdx.y;

    float acc[4][4][4];
    gemm_mainloop(Ap + (size_t)mb * 2 * 2048, Bp + (size_t)nb * 2 * 4096, 2,
                  st, tid, lane, wm, wn, acc);

    int g = lane >> 2, q = lane & 3;
    #pragma unroll
    for (int mi = 0; mi < 4; mi++) {
        int mA = mb * 128 + wm * 64 + mi * 16 + g;
        int mB = mA + 8;
        #pragma unroll
        for (int ni = 0; ni < 4; ni++) {
            int cc = wn * 32 + (ni >> 1) * 16 + (ni & 1) * 8 + q * 2;
            int n = nb * BN_ + cc;
            xg[(size_t)mA * G4_ + n]     = acc[mi][ni][0];
            xg[(size_t)mA * G4_ + n + 1] = acc[mi][ni][1];
            xg[(size_t)mB * G4_ + n]     = acc[mi][ni][2];
            xg[(size_t)mB * G4_ + n + 1] = acc[mi][ni][3];
        }
    }
}

// ---------------- K4: hid = hs @ W1^T + b1, epilogue writes K5 A-fragments directly ----------------
__global__ __launch_bounds__(512, 1)
void gemm_hid(const uint4* __restrict__ Ap, const uint4* __restrict__ Bp,
              const float* __restrict__ b1, uint4* __restrict__ outp) {
    __shared__ float b1s[BN_];
    extern __shared__ char st[];
    int tid = threadIdx.x, lane = tid & 31, warp = tid >> 5;
    int wm = warp >> 3, wn = warp & 7;
    int mb = blockIdx.x, nb = blockIdx.y;

    if (tid < BN_) b1s[tid] = b1[nb * BN_ + tid];

    float acc[4][4][4];
    gemm_mainloop(Ap + (size_t)mb * 4 * 2048, Bp + (size_t)nb * 4 * 4096, 4,
                  st, tid, lane, wm, wn, acc);

    int q = lane & 3;
    #pragma unroll
    for (int mi = 0; mi < 4; mi++) {
        int mA = mb * 128 + wm * 64 + mi * 16;   // tile base row
        int mb5 = mA >> 7, tm = (mA >> 4) & 7;
        #pragma unroll
        for (int j = 0; j < 2; j++) {
            int kt = nb * 16 + wn * 2 + j;       // n16 index = hid k16 index
            int kc = kt >> 3, k16 = kt & 7;
            int c = wn * 32 + j * 16 + 2 * q;    // local bias col
            float* L = acc[mi][2 * j];
            float* Hh = acc[mi][2 * j + 1];
            uint4 o;
            o.x = pack2(L[0] + b1s[c],      L[1] + b1s[c + 1]);
            o.y = pack2(L[2] + b1s[c],      L[3] + b1s[c + 1]);
            o.z = pack2(Hh[0] + b1s[c + 8], Hh[1] + b1s[c + 9]);
            o.w = pack2(Hh[2] + b1s[c + 8], Hh[3] + b1s[c + 9]);
            outp[((((mb5 * 8 + kc) * 8 + k16) * 8 + tm) << 5) + lane] = o;
        }
    }
}

// ---------------- K5: logits = hid @ W2^T + b2 ----------------
__global__ __launch_bounds__(512, 1)
void logits_mma(const uint4* __restrict__ Ap, const uint4* __restrict__ Bp,
                const float* __restrict__ b2, float* __restrict__ out) {
    __shared__ float b2s[BN_];
    extern __shared__ char st[];
    int tid = threadIdx.x, lane = tid & 31, warp = tid >> 5;
    int wm = warp >> 3, wn = warp & 7;
    int mb = blockIdx.x, nb = blockIdx.y;

    if (tid < BN_) { int v = nb * BN_ + tid; b2s[tid] = (v < V_) ? b2[v] : 0.f; }

    float acc[4][4][4];
    gemm_mainloop(Ap + (size_t)mb * 8 * 2048, Bp + (size_t)nb * 8 * 4096, 8,
                  st, tid, lane, wm, wn, acc);

    // epilogue: m = t*B+b ; out[b][t][v]
    int g = lane >> 2, q = lane & 3;
    #pragma unroll
    for (int mi = 0; mi < 4; mi++) {
        int mA = mb * 128 + wm * 64 + mi * 16 + g;
        int mB = mA + 8;
        size_t offA = ((size_t)(mA & 31) * T_ + (size_t)(mA >> 5)) * (size_t)V_;
        size_t offB = ((size_t)(mB & 31) * T_ + (size_t)(mB >> 5)) * (size_t)V_;
        #pragma unroll
        for (int ni = 0; ni < 4; ni++) {
            int cc = wn * 32 + (ni >> 1) * 16 + (ni & 1) * 8 + q * 2;
            int n = nb * BN_ + cc;
            if (n < V_) {
                out[offA + n] = acc[mi][ni][0] + b2s[cc];
                out[offB + n] = acc[mi][ni][2] + b2s[cc];
                if (n + 1 < V_) {
                    out[offA + n + 1] = acc[mi][ni][1] + b2s[cc + 1];
                    out[offB + n + 1] = acc[mi][ni][3] + b2s[cc + 1];
                }
            }
        }
    }
}

// ---------------- launch ----------------
extern "C" void kernel_launch(void* const* d_in, const int* in_sizes, int n_in,
                              void* d_out, int out_size) {
    const float* features = (const float*)d_in[0];
    const int*   captions = (const int*)d_in[1];
    const float* emb      = (const float*)d_in[2];
    const float* W_ih     = (const float*)d_in[3];
    const float* W_hh     = (const float*)d_in[4];
    const float* b_ih     = (const float*)d_in[5];
    const float* b_hh     = (const float*)d_in[6];
    const float* W1       = (const float*)d_in[7];
    const float* b1       = (const float*)d_in[8];
    const float* W2       = (const float*)d_in[9];
    const float* b2       = (const float*)d_in[10];
    float* out = (float*)d_out;

    void *p_base, *p_xg, *p_hs, *p_embp, *p_wihp, *p_hsp, *p_w1p, *p_hidp, *p_w2p;
    cudaGetSymbolAddress(&p_base, g_base);
    cudaGetSymbolAddress(&p_xg,   g_xg);
    cudaGetSymbolAddress(&p_hs,   g_hs);
    cudaGetSymbolAddress(&p_embp, g_embp);
    cudaGetSymbolAddress(&p_wihp, g_wihp);
    cudaGetSymbolAddress(&p_hsp,  g_hsp);
    cudaGetSymbolAddress(&p_w1p,  g_w1p);
    cudaGetSymbolAddress(&p_hidp, g_hidp);
    cudaGetSymbolAddress(&p_w2p,  g_w2p);
    float* base = (float*)p_base;
    float* xg   = (float*)p_xg;
    float* hs   = (float*)p_hs;

    cudaFuncSetAttribute(gemm_xg,    cudaFuncAttributeMaxDynamicSharedMemorySize, SMEM_DYN);
    cudaFuncSetAttribute(gemm_hid,   cudaFuncAttributeMaxDynamicSharedMemorySize, SMEM_DYN);
    cudaFuncSetAttribute(logits_mma, cudaFuncAttributeMaxDynamicSharedMemorySize, SMEM_DYN);

    // Side stream + events for fork-join capture (created once, on the first
    // uncaptured correctness call; reused as graph nodes thereafter).
    static cudaStream_t s2 = nullptr;
    static cudaEvent_t evFork = nullptr, evJoin = nullptr;
    if (s2 == nullptr) {
        cudaStreamCreateWithFlags(&s2, cudaStreamNonBlocking);
        cudaEventCreateWithFlags(&evFork, cudaEventDisableTiming);
        cudaEventCreateWithFlags(&evJoin, cudaEventDisableTiming);
    }

    // ---- fork: W2 B-frag permute (only K5 depends on it) runs on s2 ----
    cudaEventRecord(evFork, 0);
    cudaStreamWaitEvent(s2, evFork, 0);
    permB_g<<<4096, 256, 0, s2>>>(W2, (uint4*)p_w2p, H2_, 8, VPAD2_, V_);
    cudaEventRecord(evJoin, s2);

    // ---- main-stream chain (independent of W2) ----
    // prep: W_ih B-frags (K=256, kcnt=2, N=2048)
    permB_g<<<256, 256>>>(W_ih, (uint4*)p_wihp, E_, 2, G4_, G4_);
    // prep: W1 B-frags (K=512, kcnt=4, N=1024)
    permB_g<<<256, 256>>>(W1, (uint4*)p_w1p, H_, 4, H2_, H2_);
    // prep: gathered emb A-frags
    permA_emb<<<256, 256>>>(emb, captions, (uint4*)p_embp);

    // K1: base gates
    base_kernel<<<B_, 256>>>(features, W_hh, b_ih, b_hh, base);

    // K2: xg = emb_gathered @ W_ih^T  (fp16 mma)
    {
        dim3 grid(M_ / BM_, G4_ / BN_);   // (16, 8)
        gemm_xg<<<grid, 512, SMEM_DYN>>>((const uint4*)p_embp, (const uint4*)p_wihp, xg);
    }

    // K3: LSTM scan
    lstm_scan<<<128, 128>>>(xg, base, hs);

    // prep: hs A-frags (K=512, kcnt=4)
    permA_g<<<256, 256>>>(hs, (uint4*)p_hsp, M_, H_, 4);

    // K4: hid = hs @ W1^T + b1 -> writes K5 A-fragments directly (fp16)
    {
        dim3 grid(M_ / BM_, H2_ / BN_);   // (16, 4)
        gemm_hid<<<grid, 512, SMEM_DYN>>>((const uint4*)p_hsp, (const uint4*)p_w1p, b1,
                                          (uint4*)p_hidp);
    }

    // ---- join: K5 needs both the chain (hidp) and s2 (w2p) ----
    cudaStreamWaitEvent(0, evJoin, 0);

    // K5: logits
    {
        dim3 grid(M_ / BM_, VPAD2_ / BN_);   // (16, 197)
        logits_mma<<<grid, 512, SMEM_DYN>>>((const uint4*)p_hidp, (const uint4*)p_w2p, b2, out);
    }
}